// round 14
// baseline (speedup 1.0000x reference)
#include <cuda_runtime.h>
#include <cuda_device_runtime_api.h>

// Problem constants
#define BB 16
#define CC 64
#define HH 256
#define WW 256
#define HW (HH*WW)
#define KPOS 9          // 3x3
#define JDIM (CC*KPOS)  // 576

// Scratch (no allocation allowed in kernel_launch)
__device__ __align__(16) float g_avg[BB*CC];   // 1024 channel means

// ---------------------------------------------------------------------------
// Kernel 1: per-(b,c) spatial mean. At DRAM roofline (81% / 6.45 TB/s).
// Triggers programmatic launch completion so the conv kernel's independent
// prologue (x loads) can overlap this kernel's tail drain.
// ---------------------------------------------------------------------------
__global__ void avg_kernel(const float* __restrict__ x) {
    const int bc = blockIdx.x;
    const float4* p = reinterpret_cast<const float4*>(x + (size_t)bc * HW);
    const int t = threadIdx.x;     // 0..255
    float s = 0.f;
    #pragma unroll 8
    for (int i = 0; i < 64; ++i) {
        float4 v = p[i * 256 + t];
        s += (v.x + v.y) + (v.z + v.w);
    }
    __shared__ float red[256];
    red[t] = s;
    __syncthreads();
    #pragma unroll
    for (int off = 128; off > 0; off >>= 1) {
        if (t < off) red[t] += red[t + off];
        __syncthreads();
    }
    if (t == 0) g_avg[bc] = red[0] * (1.0f / (float)HW);
    cudaTriggerProgrammaticLaunchCompletion();
}

// ---------------------------------------------------------------------------
// Kernel 2: depthwise 3x3 conv + conv_bias, fused with (x-y)*fs*x + y.
// PDL secondary: first two row loads (independent of g_avg) are issued,
// then cudaGridDependencySynchronize() gates the g_avg read.
// Weight path (PROVEN R12): warps 0..4, 9x16 distributed dot, 16-lane shfl
// reduce, sigmoid, smem, one __syncthreads.
// Conv body (PROVEN R12, 80.4us @ 6053 GB/s): TR=32, 4 cols/thread,
// coalesced LDG.128/STG.128, halo = 2 scalar LDGs (L1 hits), rolling
// 3-row x 6-col register window, streaming stores. (R13's TR=64 regressed.)
// ---------------------------------------------------------------------------
#define TR 32

__device__ __forceinline__ void load_row6(const float* __restrict__ xp,
                                          int g, int col0,
                                          float& l, float4& v, float& r) {
    v = make_float4(0.f, 0.f, 0.f, 0.f);
    l = 0.f; r = 0.f;
    if ((unsigned)g < HH) {
        const float* rowp = xp + (size_t)g * WW;
        v = *reinterpret_cast<const float4*>(rowp + col0);
        if (col0 > 0)         l = __ldg(rowp + col0 - 1);
        if (col0 < WW - 4)    r = __ldg(rowp + col0 + 4);
    }
}

__global__ void __launch_bounds__(256) conv_kernel(
        const float* __restrict__ x,
        const float* __restrict__ w1,
        const float* __restrict__ b1,
        const float* __restrict__ fscale,
        const float* __restrict__ conv_bias,
        float* __restrict__ out) {
    const int bc   = blockIdx.y;          // 0..1023
    const int b    = bc >> 6;
    const int c    = bc & (CC - 1);
    const int row0 = blockIdx.x * TR;
    const int t    = threadIdx.x;         // 0..255
    const int cg   = t & 63;              // cols [4cg, 4cg+3]
    const int rs   = t >> 6;              // row slice 0..3 (8 rows each)
    const int g0   = row0 + rs * 8;
    const int col0 = cg * 4;

    const float* xp = x + (size_t)bc * HW;

    // Independent prologue: issue the first two (long-latency) row loads
    // BEFORE waiting on the avg kernel — overlaps its tail drain.
    float  al, ar, bl, br;
    float4 av, bv;
    load_row6(xp, g0 - 1, col0, al, av, ar);
    load_row6(xp, g0,     col0, bl, bv, br);

    // Wait for the primary (avg) grid before touching g_avg.
    cudaGridDependencySynchronize();

    // Distributed inline weights over whole warps 0..4 (t < 160).
    __shared__ float wsh[KPOS];
    if (t < 160) {                        // warps 0..4, all 32 lanes active
        int widx = t >> 4;                // 0..9
        if (widx > 8) widx = 8;           // lanes 144..159 duplicate widx=8
        const int seg = t & 15;           // 0..15 (4 channels each)
        const int j   = c * KPOS + widx;
        const float4 a4 = reinterpret_cast<const float4*>(g_avg + b * CC)[seg];
        const float4 q4 = __ldg(reinterpret_cast<const float4*>(
                                    w1 + (size_t)j * CC) + seg);
        float acc = a4.x*q4.x + a4.y*q4.y + a4.z*q4.z + a4.w*q4.w;
        acc += __shfl_down_sync(0xffffffffu, acc, 8, 16);
        acc += __shfl_down_sync(0xffffffffu, acc, 4, 16);
        acc += __shfl_down_sync(0xffffffffu, acc, 2, 16);
        acc += __shfl_down_sync(0xffffffffu, acc, 1, 16);
        if (seg == 0)                     // t=144 rewrites wsh[8] (same value)
            wsh[widx] = 1.0f / (1.0f + expf(-(acc + __ldg(b1 + j))));
    }
    __syncthreads();

    const float w0 = wsh[0], w1v = wsh[1], w2 = wsh[2];
    const float w3 = wsh[3], w4  = wsh[4], w5 = wsh[5];
    const float w6 = wsh[6], w7  = wsh[7], w8 = wsh[8];
    const float cb = __ldg(conv_bias + c);
    const float fs = __ldg(fscale + c);

    float* op = out + (size_t)bc * HW + (size_t)g0 * WW + col0;

    #pragma unroll
    for (int r = 0; r < 8; ++r) {
        float  cl, cr;
        float4 cv;
        load_row6(xp, g0 + r + 1, col0, cl, cv, cr);

        float4 o;
        {   // col0
            float y = cb + w0*al   + w1v*av.x + w2*av.y
                         + w3*bl   + w4 *bv.x + w5*bv.y
                         + w6*cl   + w7 *cv.x + w8*cv.y;
            const float xv = bv.x;
            o.x = (xv - y) * fs * xv + y;
        }
        {   // col0+1
            float y = cb + w0*av.x + w1v*av.y + w2*av.z
                         + w3*bv.x + w4 *bv.y + w5*bv.z
                         + w6*cv.x + w7 *cv.y + w8*cv.z;
            const float xv = bv.y;
            o.y = (xv - y) * fs * xv + y;
        }
        {   // col0+2
            float y = cb + w0*av.y + w1v*av.z + w2*av.w
                         + w3*bv.y + w4 *bv.z + w5*bv.w
                         + w6*cv.y + w7 *cv.z + w8*cv.w;
            const float xv = bv.z;
            o.z = (xv - y) * fs * xv + y;
        }
        {   // col0+3
            float y = cb + w0*av.z + w1v*av.w + w2*ar
                         + w3*bv.z + w4 *bv.w + w5*br
                         + w6*cv.z + w7 *cv.w + w8*cr;
            const float xv = bv.w;
            o.w = (xv - y) * fs * xv + y;
        }
        __stcs(reinterpret_cast<float4*>(op + (size_t)r * WW), o);

        al = bl; av = bv; ar = br;
        bl = cl; bv = cv; br = cr;
    }
}

// ---------------------------------------------------------------------------
// Launch: x, w1, b1, fscale, conv_bias (metadata order); out fp32.
// conv is launched as a PDL secondary so its prologue overlaps avg's tail.
// ---------------------------------------------------------------------------
extern "C" void kernel_launch(void* const* d_in, const int* in_sizes, int n_in,
                              void* d_out, int out_size) {
    const float* x         = (const float*)d_in[0];
    const float* w1        = (const float*)d_in[1];
    const float* b1        = (const float*)d_in[2];
    const float* fscale    = (const float*)d_in[3];
    const float* conv_bias = (const float*)d_in[4];
    float* out = (float*)d_out;

    avg_kernel<<<BB * CC, 256>>>(x);

    cudaLaunchConfig_t cfg = {};
    cfg.gridDim  = dim3(HH / TR, BB * CC);
    cfg.blockDim = dim3(256);
    cudaLaunchAttribute attr[1];
    attr[0].id = cudaLaunchAttributeProgrammaticStreamSerialization;
    attr[0].val.programmaticStreamSerializationAllowed = 1;
    cfg.attrs = attr;
    cfg.numAttrs = 1;
    cudaLaunchKernelEx(&cfg, conv_kernel, x, w1, b1, fscale, conv_bias, out);
}

// round 15
// speedup vs baseline: 1.1223x; 1.1223x over previous
#include <cuda_runtime.h>

// Problem constants
#define BB 16
#define CC 64
#define HH 256
#define WW 256
#define HW (HH*WW)
#define KPOS 9          // 3x3
#define JDIM (CC*KPOS)  // 576

// Scratch (no allocation allowed in kernel_launch)
__device__ __align__(16) float g_avg[BB*CC];   // 1024 channel means

// ---------------------------------------------------------------------------
// Kernel 1: per-(b,c) spatial mean. At DRAM roofline (81% / 6.45 TB/s).
// ---------------------------------------------------------------------------
__global__ void avg_kernel(const float* __restrict__ x) {
    const int bc = blockIdx.x;
    const float4* p = reinterpret_cast<const float4*>(x + (size_t)bc * HW);
    const int t = threadIdx.x;     // 0..255
    float s = 0.f;
    #pragma unroll 8
    for (int i = 0; i < 64; ++i) {
        float4 v = p[i * 256 + t];
        s += (v.x + v.y) + (v.z + v.w);
    }
    __shared__ float red[256];
    red[t] = s;
    __syncthreads();
    #pragma unroll
    for (int off = 128; off > 0; off >>= 1) {
        if (t < off) red[t] += red[t + off];
        __syncthreads();
    }
    if (t == 0) g_avg[bc] = red[0] * (1.0f / (float)HW);
}

// ---------------------------------------------------------------------------
// Kernel 2: depthwise 3x3 conv + conv_bias, fused with (x-y)*fs*x + y.
// Inline dynamic weights (PROVEN R12): warps 0..4 (t<160), 9 weights x 16
// segments, one float4 FMA each, 16-lane shfl reduce, sigmoid, smem, one
// __syncthreads — overlapped with the first two row loads.
// Conv body (PROVEN R12, 80.4us @ 6053 GB/s): TR=32, 4 cols/thread, fully
// coalesced LDG.128/STG.128, halo = 2 scalar LDGs (L1 hits), rolling
// 3-row x 6-col register window, streaming stores.
// Bracketed experiments: TR=64 (R13) regressed (+6us, longer tails);
// PDL overlap (R14) regressed (+16us, two DRAM-bound kernels interfere).
// This exact configuration is the measured optimum.
// ---------------------------------------------------------------------------
#define TR 32

__device__ __forceinline__ void load_row6(const float* __restrict__ xp,
                                          int g, int col0,
                                          float& l, float4& v, float& r) {
    v = make_float4(0.f, 0.f, 0.f, 0.f);
    l = 0.f; r = 0.f;
    if ((unsigned)g < HH) {
        const float* rowp = xp + (size_t)g * WW;
        v = *reinterpret_cast<const float4*>(rowp + col0);
        if (col0 > 0)         l = __ldg(rowp + col0 - 1);
        if (col0 < WW - 4)    r = __ldg(rowp + col0 + 4);
    }
}

__global__ void __launch_bounds__(256) conv_kernel(
        const float* __restrict__ x,
        const float* __restrict__ w1,
        const float* __restrict__ b1,
        const float* __restrict__ fscale,
        const float* __restrict__ conv_bias,
        float* __restrict__ out) {
    const int bc   = blockIdx.y;          // 0..1023
    const int b    = bc >> 6;
    const int c    = bc & (CC - 1);
    const int row0 = blockIdx.x * TR;
    const int t    = threadIdx.x;         // 0..255
    const int cg   = t & 63;              // cols [4cg, 4cg+3]
    const int rs   = t >> 6;              // row slice 0..3 (8 rows each)
    const int g0   = row0 + rs * 8;
    const int col0 = cg * 4;

    const float* xp = x + (size_t)bc * HW;

    // Issue the first two (long-latency) row loads before the weight work.
    float  al, ar, bl, br;
    float4 av, bv;
    load_row6(xp, g0 - 1, col0, al, av, ar);
    load_row6(xp, g0,     col0, bl, bv, br);

    // Distributed inline weights over whole warps 0..4 (t < 160).
    __shared__ float wsh[KPOS];
    if (t < 160) {                        // warps 0..4, all 32 lanes active
        int widx = t >> 4;                // 0..9
        if (widx > 8) widx = 8;           // lanes 144..159 duplicate widx=8
        const int seg = t & 15;           // 0..15 (4 channels each)
        const int j   = c * KPOS + widx;
        const float4 a4 = reinterpret_cast<const float4*>(g_avg + b * CC)[seg];
        const float4 q4 = __ldg(reinterpret_cast<const float4*>(
                                    w1 + (size_t)j * CC) + seg);
        float acc = a4.x*q4.x + a4.y*q4.y + a4.z*q4.z + a4.w*q4.w;
        acc += __shfl_down_sync(0xffffffffu, acc, 8, 16);
        acc += __shfl_down_sync(0xffffffffu, acc, 4, 16);
        acc += __shfl_down_sync(0xffffffffu, acc, 2, 16);
        acc += __shfl_down_sync(0xffffffffu, acc, 1, 16);
        if (seg == 0)                     // t=144 rewrites wsh[8] (same value)
            wsh[widx] = 1.0f / (1.0f + expf(-(acc + __ldg(b1 + j))));
    }
    __syncthreads();

    const float w0 = wsh[0], w1v = wsh[1], w2 = wsh[2];
    const float w3 = wsh[3], w4  = wsh[4], w5 = wsh[5];
    const float w6 = wsh[6], w7  = wsh[7], w8 = wsh[8];
    const float cb = __ldg(conv_bias + c);
    const float fs = __ldg(fscale + c);

    float* op = out + (size_t)bc * HW + (size_t)g0 * WW + col0;

    #pragma unroll
    for (int r = 0; r < 8; ++r) {
        float  cl, cr;
        float4 cv;
        load_row6(xp, g0 + r + 1, col0, cl, cv, cr);

        float4 o;
        {   // col0
            float y = cb + w0*al   + w1v*av.x + w2*av.y
                         + w3*bl   + w4 *bv.x + w5*bv.y
                         + w6*cl   + w7 *cv.x + w8*cv.y;
            const float xv = bv.x;
            o.x = (xv - y) * fs * xv + y;
        }
        {   // col0+1
            float y = cb + w0*av.x + w1v*av.y + w2*av.z
                         + w3*bv.x + w4 *bv.y + w5*bv.z
                         + w6*cv.x + w7 *cv.y + w8*cv.z;
            const float xv = bv.y;
            o.y = (xv - y) * fs * xv + y;
        }
        {   // col0+2
            float y = cb + w0*av.y + w1v*av.z + w2*av.w
                         + w3*bv.y + w4 *bv.z + w5*bv.w
                         + w6*cv.y + w7 *cv.z + w8*cv.w;
            const float xv = bv.z;
            o.z = (xv - y) * fs * xv + y;
        }
        {   // col0+3
            float y = cb + w0*av.z + w1v*av.w + w2*ar
                         + w3*bv.z + w4 *bv.w + w5*br
                         + w6*cv.z + w7 *cv.w + w8*cr;
            const float xv = bv.w;
            o.w = (xv - y) * fs * xv + y;
        }
        __stcs(reinterpret_cast<float4*>(op + (size_t)r * WW), o);

        al = bl; av = bv; ar = br;
        bl = cl; bv = cv; br = cr;
    }
}

// ---------------------------------------------------------------------------
// Launch: x, w1, b1, fscale, conv_bias (metadata order); out fp32.
// ---------------------------------------------------------------------------
extern "C" void kernel_launch(void* const* d_in, const int* in_sizes, int n_in,
                              void* d_out, int out_size) {
    const float* x         = (const float*)d_in[0];
    const float* w1        = (const float*)d_in[1];
    const float* b1        = (const float*)d_in[2];
    const float* fscale    = (const float*)d_in[3];
    const float* conv_bias = (const float*)d_in[4];
    float* out = (float*)d_out;

    avg_kernel<<<BB * CC, 256>>>(x);
    conv_kernel<<<dim3(HH / TR, BB * CC), 256>>>(x, w1, b1, fscale, conv_bias, out);
}

// round 16
// speedup vs baseline: 1.1262x; 1.0035x over previous
#include <cuda_runtime.h>
#include <cuda_device_runtime_api.h>

// Problem constants
#define BB 16
#define CC 64
#define HH 256
#define WW 256
#define HW (HH*WW)
#define KPOS 9          // 3x3
#define JDIM (CC*KPOS)  // 576

// Scratch (no allocation allowed in kernel_launch)
__device__ __align__(16) float g_avg[BB*CC];   // 1024 channel means

// ---------------------------------------------------------------------------
// Kernel 1: per-(b,c) spatial mean. At DRAM roofline (81% / 6.45 TB/s).
// Fires programmatic completion at the end so the pre-placed conv CTAs
// (blocked at their top-of-kernel dependency sync) start instantly.
// ---------------------------------------------------------------------------
__global__ void avg_kernel(const float* __restrict__ x) {
    const int bc = blockIdx.x;
    const float4* p = reinterpret_cast<const float4*>(x + (size_t)bc * HW);
    const int t = threadIdx.x;     // 0..255
    float s = 0.f;
    #pragma unroll 8
    for (int i = 0; i < 64; ++i) {
        float4 v = p[i * 256 + t];
        s += (v.x + v.y) + (v.z + v.w);
    }
    __shared__ float red[256];
    red[t] = s;
    __syncthreads();
    #pragma unroll
    for (int off = 128; off > 0; off >>= 1) {
        if (t < off) red[t] += red[t + off];
        __syncthreads();
    }
    if (t == 0) g_avg[bc] = red[0] * (1.0f / (float)HW);
    cudaTriggerProgrammaticLaunchCompletion();
}

// ---------------------------------------------------------------------------
// Kernel 2: depthwise 3x3 conv + conv_bias, fused with (x-y)*fs*x + y.
// PDL secondary with the dependency sync at the VERY TOP (before any memory
// access): conv CTAs get placed/resident during avg's tail drain but issue
// ZERO traffic until avg completes — launch ramp hidden, no interference.
// (R14's regression came from loads issued before the sync.)
// Weight path + conv body: PROVEN R12/R15 (80.0us @ 6088 GB/s).
// ---------------------------------------------------------------------------
#define TR 32

__device__ __forceinline__ void load_row6(const float* __restrict__ xp,
                                          int g, int col0,
                                          float& l, float4& v, float& r) {
    v = make_float4(0.f, 0.f, 0.f, 0.f);
    l = 0.f; r = 0.f;
    if ((unsigned)g < HH) {
        const float* rowp = xp + (size_t)g * WW;
        v = *reinterpret_cast<const float4*>(rowp + col0);
        if (col0 > 0)         l = __ldg(rowp + col0 - 1);
        if (col0 < WW - 4)    r = __ldg(rowp + col0 + 4);
    }
}

__global__ void __launch_bounds__(256) conv_kernel(
        const float* __restrict__ x,
        const float* __restrict__ w1,
        const float* __restrict__ b1,
        const float* __restrict__ fscale,
        const float* __restrict__ conv_bias,
        float* __restrict__ out) {
    // Block ALL memory traffic until the avg grid completes. CTAs are
    // resident and ready; the wait is a HW sleep (no BW consumed).
    cudaGridDependencySynchronize();

    const int bc   = blockIdx.y;          // 0..1023
    const int b    = bc >> 6;
    const int c    = bc & (CC - 1);
    const int row0 = blockIdx.x * TR;
    const int t    = threadIdx.x;         // 0..255
    const int cg   = t & 63;              // cols [4cg, 4cg+3]
    const int rs   = t >> 6;              // row slice 0..3 (8 rows each)
    const int g0   = row0 + rs * 8;
    const int col0 = cg * 4;

    const float* xp = x + (size_t)bc * HW;

    // Issue the first two (long-latency) row loads before the weight work.
    float  al, ar, bl, br;
    float4 av, bv;
    load_row6(xp, g0 - 1, col0, al, av, ar);
    load_row6(xp, g0,     col0, bl, bv, br);

    // Distributed inline weights over whole warps 0..4 (t < 160).
    __shared__ float wsh[KPOS];
    if (t < 160) {                        // warps 0..4, all 32 lanes active
        int widx = t >> 4;                // 0..9
        if (widx > 8) widx = 8;           // lanes 144..159 duplicate widx=8
        const int seg = t & 15;           // 0..15 (4 channels each)
        const int j   = c * KPOS + widx;
        const float4 a4 = reinterpret_cast<const float4*>(g_avg + b * CC)[seg];
        const float4 q4 = __ldg(reinterpret_cast<const float4*>(
                                    w1 + (size_t)j * CC) + seg);
        float acc = a4.x*q4.x + a4.y*q4.y + a4.z*q4.z + a4.w*q4.w;
        acc += __shfl_down_sync(0xffffffffu, acc, 8, 16);
        acc += __shfl_down_sync(0xffffffffu, acc, 4, 16);
        acc += __shfl_down_sync(0xffffffffu, acc, 2, 16);
        acc += __shfl_down_sync(0xffffffffu, acc, 1, 16);
        if (seg == 0)                     // t=144 rewrites wsh[8] (same value)
            wsh[widx] = 1.0f / (1.0f + expf(-(acc + __ldg(b1 + j))));
    }
    __syncthreads();

    const float w0 = wsh[0], w1v = wsh[1], w2 = wsh[2];
    const float w3 = wsh[3], w4  = wsh[4], w5 = wsh[5];
    const float w6 = wsh[6], w7  = wsh[7], w8 = wsh[8];
    const float cb = __ldg(conv_bias + c);
    const float fs = __ldg(fscale + c);

    float* op = out + (size_t)bc * HW + (size_t)g0 * WW + col0;

    #pragma unroll
    for (int r = 0; r < 8; ++r) {
        float  cl, cr;
        float4 cv;
        load_row6(xp, g0 + r + 1, col0, cl, cv, cr);

        float4 o;
        {   // col0
            float y = cb + w0*al   + w1v*av.x + w2*av.y
                         + w3*bl   + w4 *bv.x + w5*bv.y
                         + w6*cl   + w7 *cv.x + w8*cv.y;
            const float xv = bv.x;
            o.x = (xv - y) * fs * xv + y;
        }
        {   // col0+1
            float y = cb + w0*av.x + w1v*av.y + w2*av.z
                         + w3*bv.x + w4 *bv.y + w5*bv.z
                         + w6*cv.x + w7 *cv.y + w8*cv.z;
            const float xv = bv.y;
            o.y = (xv - y) * fs * xv + y;
        }
        {   // col0+2
            float y = cb + w0*av.y + w1v*av.z + w2*av.w
                         + w3*bv.y + w4 *bv.z + w5*bv.w
                         + w6*cv.y + w7 *cv.z + w8*cv.w;
            const float xv = bv.z;
            o.z = (xv - y) * fs * xv + y;
        }
        {   // col0+3
            float y = cb + w0*av.z + w1v*av.w + w2*ar
                         + w3*bv.z + w4 *bv.w + w5*br
                         + w6*cv.z + w7 *cv.w + w8*cr;
            const float xv = bv.w;
            o.w = (xv - y) * fs * xv + y;
        }
        __stcs(reinterpret_cast<float4*>(op + (size_t)r * WW), o);

        al = bl; av = bv; ar = br;
        bl = cl; bv = cv; br = cr;
    }
}

// ---------------------------------------------------------------------------
// Launch: x, w1, b1, fscale, conv_bias (metadata order); out fp32.
// conv is a PDL secondary; its CTAs pre-place during avg's tail drain.
// ---------------------------------------------------------------------------
extern "C" void kernel_launch(void* const* d_in, const int* in_sizes, int n_in,
                              void* d_out, int out_size) {
    const float* x         = (const float*)d_in[0];
    const float* w1        = (const float*)d_in[1];
    const float* b1        = (const float*)d_in[2];
    const float* fscale    = (const float*)d_in[3];
    const float* conv_bias = (const float*)d_in[4];
    float* out = (float*)d_out;

    avg_kernel<<<BB * CC, 256>>>(x);

    cudaLaunchConfig_t cfg = {};
    cfg.gridDim  = dim3(HH / TR, BB * CC);
    cfg.blockDim = dim3(256);
    cudaLaunchAttribute attr[1];
    attr[0].id = cudaLaunchAttributeProgrammaticStreamSerialization;
    attr[0].val.programmaticStreamSerializationAllowed = 1;
    cfg.attrs = attr;
    cfg.numAttrs = 1;
    cudaLaunchKernelEx(&cfg, conv_kernel, x, w1, b1, fscale, conv_bias, out);
}

// round 17
// speedup vs baseline: 1.1415x; 1.0136x over previous
#include <cuda_runtime.h>
#include <cuda_device_runtime_api.h>

// Problem constants
#define BB 16
#define CC 64
#define HH 256
#define WW 256
#define HW (HH*WW)
#define KPOS 9          // 3x3
#define JDIM (CC*KPOS)  // 576

// Scratch (no allocation allowed in kernel_launch)
__device__ __align__(16) float g_avg[BB*CC];   // 1024 channel means

// ---------------------------------------------------------------------------
// Kernel 1: per-(b,c) spatial mean. At DRAM roofline (81% / 6.45 TB/s).
// Runs as ONE wave (1024 CTAs resident) scanning rows 0->255 in lockstep,
// so at completion L2 holds the LAST ~120 rows of every plane.
// ---------------------------------------------------------------------------
__global__ void avg_kernel(const float* __restrict__ x) {
    const int bc = blockIdx.x;
    const float4* p = reinterpret_cast<const float4*>(x + (size_t)bc * HW);
    const int t = threadIdx.x;     // 0..255
    float s = 0.f;
    #pragma unroll 8
    for (int i = 0; i < 64; ++i) {
        float4 v = p[i * 256 + t];
        s += (v.x + v.y) + (v.z + v.w);
    }
    __shared__ float red[256];
    red[t] = s;
    __syncthreads();
    #pragma unroll
    for (int off = 128; off > 0; off >>= 1) {
        if (t < off) red[t] += red[t + off];
        __syncthreads();
    }
    if (t == 0) g_avg[bc] = red[0] * (1.0f / (float)HW);
    cudaTriggerProgrammaticLaunchCompletion();
}

// ---------------------------------------------------------------------------
// Kernel 2: depthwise 3x3 conv + conv_bias, fused with (x-y)*fs*x + y.
// PDL secondary, dependency sync at the very top (proven R16).
// L2 REVERSE-RECENCY ORDER: grid is (bc, row_tile) with the row tile index
// REVERSED, so the first conv wave reads the bottom rows of all planes —
// exactly the lines avg touched last (still L2-resident). Waves then walk
// upward through L2's LRU stripe before eviction catches up.
// Weight path + conv body: PROVEN R12/R15/R16 (80.0us @ 6.08 TB/s).
// ---------------------------------------------------------------------------
#define TR 32

__device__ __forceinline__ void load_row6(const float* __restrict__ xp,
                                          int g, int col0,
                                          float& l, float4& v, float& r) {
    v = make_float4(0.f, 0.f, 0.f, 0.f);
    l = 0.f; r = 0.f;
    if ((unsigned)g < HH) {
        const float* rowp = xp + (size_t)g * WW;
        v = *reinterpret_cast<const float4*>(rowp + col0);
        if (col0 > 0)         l = __ldg(rowp + col0 - 1);
        if (col0 < WW - 4)    r = __ldg(rowp + col0 + 4);
    }
}

__global__ void __launch_bounds__(256) conv_kernel(
        const float* __restrict__ x,
        const float* __restrict__ w1,
        const float* __restrict__ b1,
        const float* __restrict__ fscale,
        const float* __restrict__ conv_bias,
        float* __restrict__ out) {
    // Block ALL memory traffic until the avg grid completes.
    cudaGridDependencySynchronize();

    const int bc   = blockIdx.x;                      // 0..1023 (plane)
    const int b    = bc >> 6;
    const int c    = bc & (CC - 1);
    const int row0 = (int)(gridDim.y - 1 - blockIdx.y) * TR;  // reversed tiles
    const int t    = threadIdx.x;         // 0..255
    const int cg   = t & 63;              // cols [4cg, 4cg+3]
    const int rs   = t >> 6;              // row slice 0..3 (8 rows each)
    const int g0   = row0 + rs * 8;
    const int col0 = cg * 4;

    const float* xp = x + (size_t)bc * HW;

    // Issue the first two (long-latency) row loads before the weight work.
    float  al, ar, bl, br;
    float4 av, bv;
    load_row6(xp, g0 - 1, col0, al, av, ar);
    load_row6(xp, g0,     col0, bl, bv, br);

    // Distributed inline weights over whole warps 0..4 (t < 160).
    __shared__ float wsh[KPOS];
    if (t < 160) {                        // warps 0..4, all 32 lanes active
        int widx = t >> 4;                // 0..9
        if (widx > 8) widx = 8;           // lanes 144..159 duplicate widx=8
        const int seg = t & 15;           // 0..15 (4 channels each)
        const int j   = c * KPOS + widx;
        const float4 a4 = reinterpret_cast<const float4*>(g_avg + b * CC)[seg];
        const float4 q4 = __ldg(reinterpret_cast<const float4*>(
                                    w1 + (size_t)j * CC) + seg);
        float acc = a4.x*q4.x + a4.y*q4.y + a4.z*q4.z + a4.w*q4.w;
        acc += __shfl_down_sync(0xffffffffu, acc, 8, 16);
        acc += __shfl_down_sync(0xffffffffu, acc, 4, 16);
        acc += __shfl_down_sync(0xffffffffu, acc, 2, 16);
        acc += __shfl_down_sync(0xffffffffu, acc, 1, 16);
        if (seg == 0)                     // t=144 rewrites wsh[8] (same value)
            wsh[widx] = 1.0f / (1.0f + expf(-(acc + __ldg(b1 + j))));
    }
    __syncthreads();

    const float w0 = wsh[0], w1v = wsh[1], w2 = wsh[2];
    const float w3 = wsh[3], w4  = wsh[4], w5 = wsh[5];
    const float w6 = wsh[6], w7  = wsh[7], w8 = wsh[8];
    const float cb = __ldg(conv_bias + c);
    const float fs = __ldg(fscale + c);

    float* op = out + (size_t)bc * HW + (size_t)g0 * WW + col0;

    #pragma unroll
    for (int r = 0; r < 8; ++r) {
        float  cl, cr;
        float4 cv;
        load_row6(xp, g0 + r + 1, col0, cl, cv, cr);

        float4 o;
        {   // col0
            float y = cb + w0*al   + w1v*av.x + w2*av.y
                         + w3*bl   + w4 *bv.x + w5*bv.y
                         + w6*cl   + w7 *cv.x + w8*cv.y;
            const float xv = bv.x;
            o.x = (xv - y) * fs * xv + y;
        }
        {   // col0+1
            float y = cb + w0*av.x + w1v*av.y + w2*av.z
                         + w3*bv.x + w4 *bv.y + w5*bv.z
                         + w6*cv.x + w7 *cv.y + w8*cv.z;
            const float xv = bv.y;
            o.y = (xv - y) * fs * xv + y;
        }
        {   // col0+2
            float y = cb + w0*av.y + w1v*av.z + w2*av.w
                         + w3*bv.y + w4 *bv.z + w5*bv.w
                         + w6*cv.y + w7 *cv.z + w8*cv.w;
            const float xv = bv.z;
            o.z = (xv - y) * fs * xv + y;
        }
        {   // col0+3
            float y = cb + w0*av.z + w1v*av.w + w2*ar
                         + w3*bv.z + w4 *bv.w + w5*br
                         + w6*cv.z + w7 *cv.w + w8*cr;
            const float xv = bv.w;
            o.w = (xv - y) * fs * xv + y;
        }
        __stcs(reinterpret_cast<float4*>(op + (size_t)r * WW), o);

        al = bl; av = bv; ar = br;
        bl = cl; bv = cv; br = cr;
    }
}

// ---------------------------------------------------------------------------
// Launch: x, w1, b1, fscale, conv_bias (metadata order); out fp32.
// conv is a PDL secondary; grid = (planes, row_tiles) with reversed tiles.
// ---------------------------------------------------------------------------
extern "C" void kernel_launch(void* const* d_in, const int* in_sizes, int n_in,
                              void* d_out, int out_size) {
    const float* x         = (const float*)d_in[0];
    const float* w1        = (const float*)d_in[1];
    const float* b1        = (const float*)d_in[2];
    const float* fscale    = (const float*)d_in[3];
    const float* conv_bias = (const float*)d_in[4];
    float* out = (float*)d_out;

    avg_kernel<<<BB * CC, 256>>>(x);

    cudaLaunchConfig_t cfg = {};
    cfg.gridDim  = dim3(BB * CC, HH / TR);
    cfg.blockDim = dim3(256);
    cudaLaunchAttribute attr[1];
    attr[0].id = cudaLaunchAttributeProgrammaticStreamSerialization;
    attr[0].val.programmaticStreamSerializationAllowed = 1;
    cfg.attrs = attr;
    cfg.numAttrs = 1;
    cudaLaunchKernelEx(&cfg, conv_kernel, x, w1, b1, fscale, conv_bias, out);
}